// round 10
// baseline (speedup 1.0000x reference)
#include <cuda_runtime.h>
#include <cuda_bf16.h>
#include <cuda_fp16.h>
#include <cstdint>

#define BATCH 256
#define INF   1024
#define OUTF  128
#define KD    8
#define NCOLS (OUTF * KD)     // 1024
#define OUTW  (INF + OUTF)    // 1152
#define NCTAS 128

// Device scratch (no allocs allowed)
__device__ __align__(16) __half g_Mh[BATCH * NCOLS];   // M = x @ T, fp16
__device__ __nv_bfloat16 g_Abf[BATCH * INF];           // x in bf16 (K-major)
__device__ __nv_bfloat16 g_Tbf[INF * NCOLS];           // T in bf16, [k][n] layout

// Grid-barrier state (zero-initialized; ctr is reset by last arriver each use,
// flag increments monotonically forever -> replay-safe).
__device__ unsigned g_ctr[2];
__device__ unsigned g_flag[2];

__device__ __forceinline__ uint32_t smem_u32(const void* p) {
    uint32_t a;
    asm("{ .reg .u64 t; cvta.to.shared.u64 t, %1; cvt.u32.u64 %0, t; }" : "=r"(a) : "l"(p));
    return a;
}
#define SWZ128(b) ((b) ^ (((b) >> 3) & 0x70))
#define CP_ASYNC16(saddr, gptr) \
    asm volatile("cp.async.cg.shared.global [%0], [%1], 16;" :: "r"(saddr), "l"(gptr) : "memory")
#define CP_COMMIT() asm volatile("cp.async.commit_group;" ::: "memory")
#define CP_WAIT1()  asm volatile("cp.async.wait_group 1;" ::: "memory")
#define BAR_GEMM()  asm volatile("bar.sync 1, 256;" ::: "memory")

__device__ __forceinline__ void grid_barrier(int k) {
    __threadfence();          // release this thread's prior writes
    __syncthreads();          // all CTA threads' writes ordered before thread0's arrive
    if (threadIdx.x == 0) {
        const unsigned gen = atomicAdd(&g_flag[k], 0u);   // read epoch FIRST
        __threadfence();
        const unsigned old = atomicAdd(&g_ctr[k], 1u);
        if (old == NCTAS - 1) {
            atomicExch(&g_ctr[k], 0u);    // safe: all arrived; reset for next launch
            __threadfence();
            atomicAdd(&g_flag[k], 1u);    // release all
        } else {
            while (atomicAdd(&g_flag[k], 0u) == gen) { __nanosleep(32); }
        }
        __threadfence();      // acquire
    }
    __syncthreads();
}

#define STAGE_BYTES 12288
#define GEMM_SMEM   (3 * STAGE_BYTES)

// ---------------------------------------------------------------------------
// ONE fused kernel: prep -> barrier -> GEMM -> barrier -> pairwise.
// 128 CTAs x 512 threads (single wave on 148 SMs; barrier is deadlock-free).
// ---------------------------------------------------------------------------
__global__ __launch_bounds__(512) void fused_kernel(
    const float* __restrict__ x, const float* __restrict__ T,
    float* __restrict__ out)
{
    extern __shared__ __align__(1024) char dsm[];
    const int tid = threadIdx.x;
    const int bid = blockIdx.x;

    // ------------------ Phase 1: prep (T->bf16, x->out + bf16) -------------
    {
        // T: 256K float4 over 128 CTAs = 2048/CTA = 4/thread
        const int tb = bid * 2048 + tid;
        float4 tv[4];
        #pragma unroll
        for (int r = 0; r < 4; r++)
            tv[r] = reinterpret_cast<const float4*>(T)[tb + r * 512];
        // x: 64K float4 over 128 CTAs = 512/CTA = 1/thread
        const int xi = bid * 512 + tid;
        const float4 xv = reinterpret_cast<const float4*>(x)[xi];

        #pragma unroll
        for (int r = 0; r < 4; r++) {
            const int idx = tb + r * 512;
            reinterpret_cast<__nv_bfloat162*>(g_Tbf)[idx * 2] =
                __floats2bfloat162_rn(tv[r].x, tv[r].y);
            reinterpret_cast<__nv_bfloat162*>(g_Tbf)[idx * 2 + 1] =
                __floats2bfloat162_rn(tv[r].z, tv[r].w);
        }
        const int row = xi >> 8;
        const int c4  = xi & 255;
        *reinterpret_cast<float4*>(&out[row * OUTW + c4 * 4]) = xv;
        reinterpret_cast<__nv_bfloat162*>(g_Abf)[xi * 2] =
            __floats2bfloat162_rn(xv.x, xv.y);
        reinterpret_cast<__nv_bfloat162*>(g_Abf)[xi * 2 + 1] =
            __floats2bfloat162_rn(xv.z, xv.w);
    }

    grid_barrier(0);

    // ------------------ Phase 2: GEMM (warps 0-7 only) ---------------------
    // CTA tile M=32 x N=64, BK=64, 3-stage cp.async; bid -> (nt, mt).
    if (tid < 256) {
        const int wid = tid >> 5;
        const int lid = tid & 31;
        const int nt = bid & 15;     // 0..15
        const int mt = bid >> 4;     // 0..7
        const int w_m = wid >> 2;
        const int w_n = wid & 3;

        const uint32_t sbase = smem_u32(dsm);

        const __nv_bfloat16* Ag = g_Abf + (size_t)(mt * 32) * INF;
        const __nv_bfloat16* Bg = g_Tbf + nt * 64;     // [k][n], row stride NCOLS

        const int ld_row  = tid >> 3;
        const int ld_kc   = tid & 7;
        const uint32_t soff0 = SWZ128((uint32_t)(ld_row * 128 + ld_kc * 16));
        const uint32_t soff1 = SWZ128((uint32_t)((ld_row + 32) * 128 + ld_kc * 16));

        float c[2][4];
        #pragma unroll
        for (int j = 0; j < 2; j++)
            #pragma unroll
            for (int q = 0; q < 4; q++) c[j][q] = 0.0f;

        const int l7  = lid & 7;
        const int lb3 = (lid >> 3) & 1;
        const int lb4 = (lid >> 4) & 1;
        const int a_row_lane = l7 + lb3 * 8;
        const int b_row_lane = l7 + lb3 * 8;
        const int nb = w_n * 16;
        const int mb = w_m * 16;
        const uint32_t b_col_bytes = (uint32_t)(nb + 8 * lb4) * 2;

        auto load_stage = [&](int st, int k0) {
            const uint32_t sA = sbase + st * STAGE_BYTES;
            const uint32_t sB = sA + 4096;
            const __nv_bfloat16* ga = Ag + ld_row * INF + k0 + ld_kc * 8;
            const __nv_bfloat16* gb = Bg + (size_t)(k0 + ld_row) * NCOLS + ld_kc * 8;
            CP_ASYNC16(sA + soff0, ga);
            CP_ASYNC16(sB + soff0, gb);
            CP_ASYNC16(sB + soff1, gb + 32 * NCOLS);
        };

        load_stage(0, 0);   CP_COMMIT();
        load_stage(1, 64);  CP_COMMIT();

        for (int ch = 0; ch < 16; ch++) {
            CP_WAIT1();
            BAR_GEMM();
            if (ch + 2 < 16) load_stage((ch + 2) % 3, (ch + 2) * 64);
            CP_COMMIT();

            const uint32_t sA = sbase + (ch % 3) * STAGE_BYTES;
            const uint32_t sB = sA + 4096;

            #pragma unroll
            for (int s = 0; s < 4; s++) {
                uint32_t b0, b1, b2, b3;
                {
                    const uint32_t boff = SWZ128(
                        (uint32_t)((s * 16 + b_row_lane) * 128) + b_col_bytes);
                    asm volatile(
                        "ldmatrix.sync.aligned.m8n8.x4.trans.shared.b16 {%0,%1,%2,%3}, [%4];"
                        : "=r"(b0), "=r"(b1), "=r"(b2), "=r"(b3) : "r"(sB + boff));
                }
                uint32_t a0, a1, a2, a3;
                {
                    const uint32_t aoff = SWZ128(
                        (uint32_t)((mb + a_row_lane) * 128 + (s * 2 + lb4) * 16));
                    asm volatile(
                        "ldmatrix.sync.aligned.m8n8.x4.shared.b16 {%0,%1,%2,%3}, [%4];"
                        : "=r"(a0), "=r"(a1), "=r"(a2), "=r"(a3) : "r"(sA + aoff));
                }
                asm volatile(
                    "mma.sync.aligned.m16n8k16.row.col.f32.bf16.bf16.f32 "
                    "{%0,%1,%2,%3}, {%4,%5,%6,%7}, {%8,%9}, {%0,%1,%2,%3};"
                    : "+f"(c[0][0]), "+f"(c[0][1]), "+f"(c[0][2]), "+f"(c[0][3])
                    : "r"(a0), "r"(a1), "r"(a2), "r"(a3), "r"(b0), "r"(b1));
                asm volatile(
                    "mma.sync.aligned.m16n8k16.row.col.f32.bf16.bf16.f32 "
                    "{%0,%1,%2,%3}, {%4,%5,%6,%7}, {%8,%9}, {%0,%1,%2,%3};"
                    : "+f"(c[1][0]), "+f"(c[1][1]), "+f"(c[1][2]), "+f"(c[1][3])
                    : "r"(a0), "r"(a1), "r"(a2), "r"(a3), "r"(b2), "r"(b3));
            }
        }

        const int g = lid >> 2;
        const int tig = lid & 3;
        const int row = mt * 32 + mb + g;
        #pragma unroll
        for (int nf = 0; nf < 2; nf++) {
            const int col = nt * 64 + nb + nf * 8 + tig * 2;
            *reinterpret_cast<__half2*>(&g_Mh[row * NCOLS + col]) =
                __floats2half2_rn(c[nf][0], c[nf][1]);
            *reinterpret_cast<__half2*>(&g_Mh[(row + 8) * NCOLS + col]) =
                __floats2half2_rn(c[nf][2], c[nf][3]);
        }
    }

    grid_barrier(1);

    // ------------------ Phase 3: pairwise (o = bid) -------------------------
    {
        __shared__ uint4 Ms[BATCH];
        __shared__ float psum[256];

        const int o = bid;                 // 0..127
        const int i = tid & 255;
        const int h = tid >> 8;            // 0..1

        if (tid < BATCH)
            Ms[tid] = *reinterpret_cast<const uint4*>(&g_Mh[tid * NCOLS + o * KD]);
        __syncthreads();

        uint4 av = Ms[i];
        const __half2 a0 = *reinterpret_cast<__half2*>(&av.x);
        const __half2 a1 = *reinterpret_cast<__half2*>(&av.y);
        const __half2 a2 = *reinterpret_cast<__half2*>(&av.z);
        const __half2 a3 = *reinterpret_cast<__half2*>(&av.w);

        const __half2 nlog2e = __float2half2_rn(-1.44269504089f);
        __half2 acc = __float2half2_rn(0.0f);

        const int j0 = h * 128;
        #pragma unroll 8
        for (int j = j0; j < j0 + 128; j++) {
            uint4 bv = Ms[j];   // warp-uniform j -> LDS broadcast
            const __half2 s0 = __hsub2(a0, *reinterpret_cast<__half2*>(&bv.x));
            const __half2 s1 = __hsub2(a1, *reinterpret_cast<__half2*>(&bv.y));
            const __half2 s2 = __hsub2(a2, *reinterpret_cast<__half2*>(&bv.z));
            const __half2 s3 = __hsub2(a3, *reinterpret_cast<__half2*>(&bv.w));
            const __half2 t = __hadd2(__hadd2(__habs2(s0), __habs2(s1)),
                                      __hadd2(__habs2(s2), __habs2(s3)));
            const __half2 d = __hadd2(t, __lowhigh2highlow(t));
            acc = __hadd2(acc, h2exp2(__hmul2(d, nlog2e)));
        }

        const float s = __low2float(acc);

        if (h == 1) psum[i] = s;
        __syncthreads();
        if (h == 0) out[i * OUTW + INF + o] = s + psum[i] - 1.0f;
    }
}

// ---------------------------------------------------------------------------
extern "C" void kernel_launch(void* const* d_in, const int* in_sizes, int n_in,
                              void* d_out, int out_size)
{
    const float* x = (const float*)d_in[0];   // (256, 1024)
    const float* T = (const float*)d_in[1];   // (1024, 1024)
    float* out = (float*)d_out;               // (256, 1152)

    static bool attr_set = false;
    if (!attr_set) {
        cudaFuncSetAttribute(fused_kernel,
                             cudaFuncAttributeMaxDynamicSharedMemorySize, GEMM_SMEM);
        attr_set = true;
    }

    fused_kernel<<<NCTAS, 512, GEMM_SMEM>>>(x, T, out);
}

// round 11
// speedup vs baseline: 1.0770x; 1.0770x over previous
#include <cuda_runtime.h>
#include <cuda_bf16.h>
#include <cuda_fp16.h>
#include <cstdint>

#define BATCH 256
#define INF   1024
#define OUTF  128
#define KD    8
#define NCOLS (OUTF * KD)     // 1024
#define OUTW  (INF + OUTF)    // 1152

// Device scratch (no allocs allowed)
__device__ __align__(16) __half g_Mh[BATCH * NCOLS];   // M = x @ T, fp16

__device__ __forceinline__ uint32_t smem_u32(const void* p) {
    uint32_t a;
    asm("{ .reg .u64 t; cvta.to.shared.u64 t, %1; cvt.u32.u64 %0, t; }" : "=r"(a) : "l"(p));
    return a;
}
#define SWZ128(b) ((b) ^ (((b) >> 3) & 0x70))

__device__ __forceinline__ uint4 pack_bf16x8(const float4 a, const float4 b) {
    // 8 fp32 -> 8 consecutive bf16 (16B)
    uint4 r;
    __nv_bfloat162 p;
    p = __floats2bfloat162_rn(a.x, a.y); r.x = *reinterpret_cast<uint32_t*>(&p);
    p = __floats2bfloat162_rn(a.z, a.w); r.y = *reinterpret_cast<uint32_t*>(&p);
    p = __floats2bfloat162_rn(b.x, b.y); r.z = *reinterpret_cast<uint32_t*>(&p);
    p = __floats2bfloat162_rn(b.z, b.w); r.w = *reinterpret_cast<uint32_t*>(&p);
    return r;
}

// ---------------------------------------------------------------------------
// GEMM (+ x->out copy on extra CTAs). No prep kernel: fp32 loaded directly,
// converted to bf16 in registers, stored to swizzled smem; ldmatrix/mma path
// identical to the validated R8 kernel.
// CTA tile M=32 x N=64, BK=64 (16 chunks), 8 warps = 2(m) x 4(n), wtile 16x16.
// Grid: 128 GEMM CTAs (nt=bid&15, mt=bid>>4) + 16 copy CTAs (bid 128..143).
// smem: 2 x (A 4KB + B 8KB) = 24KB static.
// ---------------------------------------------------------------------------
__global__ __launch_bounds__(256) void gemm_copy_kernel(
    const float* __restrict__ x, const float* __restrict__ T,
    float* __restrict__ out, __half* __restrict__ C)
{
    const int tid = threadIdx.x;
    const int bid = blockIdx.x;

    if (bid >= 128) {
        // ---- x -> out[:, :1024] copy: 16 CTAs x 256 thr x 16 float4 ----
        const int base = (bid - 128) * 4096 + tid;
        #pragma unroll
        for (int r = 0; r < 16; r++) {
            const int idx = base + r * 256;
            const float4 v = reinterpret_cast<const float4*>(x)[idx];
            const int row = idx >> 8;
            const int c4  = idx & 255;
            *reinterpret_cast<float4*>(&out[row * OUTW + c4 * 4]) = v;
        }
        return;
    }

    __shared__ __align__(1024) char sbuf[2][12288];   // [A 4KB | B 8KB] x2

    const int wid = tid >> 5;
    const int lid = tid & 31;
    const int nt = bid & 15;     // 0..15
    const int mt = bid >> 4;     // 0..7
    const int w_m = wid >> 2;    // 0..1
    const int w_n = wid & 3;     // 0..3

    const int ld_row = tid >> 3;           // 0..31
    const int ld_kc  = tid & 7;            // 16B unit
    const uint32_t soff0 = SWZ128((uint32_t)(ld_row * 128 + ld_kc * 16));
    const uint32_t soff1 = SWZ128((uint32_t)((ld_row + 32) * 128 + ld_kc * 16));

    // Global base pointers for this thread's load slots.
    const float* gA = x + (size_t)(mt * 32 + ld_row) * INF + ld_kc * 8;
    const float* gB = T + (size_t)ld_row * NCOLS + nt * 64 + ld_kc * 8;

    float c[2][4];
    #pragma unroll
    for (int j = 0; j < 2; j++)
        #pragma unroll
        for (int q = 0; q < 4; q++) c[j][q] = 0.0f;

    const int l7  = lid & 7;
    const int lb3 = (lid >> 3) & 1;
    const int lb4 = (lid >> 4) & 1;
    const int a_row_lane = l7 + lb3 * 8;
    const int b_row_lane = l7 + lb3 * 8;
    const int nb = w_n * 16;
    const int mb = w_m * 16;
    const uint32_t b_col_bytes = (uint32_t)(nb + 8 * lb4) * 2;

    const uint32_t sbase0 = smem_u32(sbuf[0]);
    const uint32_t sbase1 = smem_u32(sbuf[1]);

    // ---- register-staged loaders (6 independent LDG.128 per chunk) ----
    float4 fA0[2], fB0[4], fA1[2], fB1[4];

    auto load_regs = [&](int ch, float4* fA, float4* fB) {
        const int k0 = ch * 64;
        fA[0] = *reinterpret_cast<const float4*>(gA + k0);
        fA[1] = *reinterpret_cast<const float4*>(gA + k0 + 4);
        const float* gb = gB + (size_t)k0 * NCOLS;
        fB[0] = *reinterpret_cast<const float4*>(gb);
        fB[1] = *reinterpret_cast<const float4*>(gb + 4);
        fB[2] = *reinterpret_cast<const float4*>(gb + 32 * NCOLS);
        fB[3] = *reinterpret_cast<const float4*>(gb + 32 * NCOLS + 4);
    };
    auto sts_stage = [&](int b, const float4* fA, const float4* fB) {
        char* pA = sbuf[b];
        char* pB = sbuf[b] + 4096;
        *reinterpret_cast<uint4*>(pA + soff0) = pack_bf16x8(fA[0], fA[1]);
        *reinterpret_cast<uint4*>(pB + soff0) = pack_bf16x8(fB[0], fB[1]);
        *reinterpret_cast<uint4*>(pB + soff1) = pack_bf16x8(fB[2], fB[3]);
    };
    auto compute = [&](uint32_t sA) {
        const uint32_t sB = sA + 4096;
        #pragma unroll
        for (int s = 0; s < 4; s++) {
            uint32_t b0, b1, b2, b3;
            {
                const uint32_t boff = SWZ128(
                    (uint32_t)((s * 16 + b_row_lane) * 128) + b_col_bytes);
                asm volatile(
                    "ldmatrix.sync.aligned.m8n8.x4.trans.shared.b16 {%0,%1,%2,%3}, [%4];"
                    : "=r"(b0), "=r"(b1), "=r"(b2), "=r"(b3) : "r"(sB + boff));
            }
            uint32_t a0, a1, a2, a3;
            {
                const uint32_t aoff = SWZ128(
                    (uint32_t)((mb + a_row_lane) * 128 + (s * 2 + lb4) * 16));
                asm volatile(
                    "ldmatrix.sync.aligned.m8n8.x4.shared.b16 {%0,%1,%2,%3}, [%4];"
                    : "=r"(a0), "=r"(a1), "=r"(a2), "=r"(a3) : "r"(sA + aoff));
            }
            asm volatile(
                "mma.sync.aligned.m16n8k16.row.col.f32.bf16.bf16.f32 "
                "{%0,%1,%2,%3}, {%4,%5,%6,%7}, {%8,%9}, {%0,%1,%2,%3};"
                : "+f"(c[0][0]), "+f"(c[0][1]), "+f"(c[0][2]), "+f"(c[0][3])
                : "r"(a0), "r"(a1), "r"(a2), "r"(a3), "r"(b0), "r"(b1));
            asm volatile(
                "mma.sync.aligned.m16n8k16.row.col.f32.bf16.bf16.f32 "
                "{%0,%1,%2,%3}, {%4,%5,%6,%7}, {%8,%9}, {%0,%1,%2,%3};"
                : "+f"(c[1][0]), "+f"(c[1][1]), "+f"(c[1][2]), "+f"(c[1][3])
                : "r"(a0), "r"(a1), "r"(a2), "r"(a3), "r"(b2), "r"(b3));
        }
    };

    load_regs(0, fA0, fB0);
    load_regs(1, fA1, fB1);

    #pragma unroll 1
    for (int it = 0; it < 8; it++) {
        const int ch = it * 2;
        // even chunk -> buffer 0
        sts_stage(0, fA0, fB0);
        if (ch + 2 < 16) load_regs(ch + 2, fA0, fB0);
        __syncthreads();
        compute(sbase0);
        // odd chunk -> buffer 1
        sts_stage(1, fA1, fB1);
        if (ch + 3 < 16) load_regs(ch + 3, fA1, fB1);
        __syncthreads();
        compute(sbase1);
    }

    const int g = lid >> 2;
    const int tig = lid & 3;
    const int row = mt * 32 + mb + g;
    #pragma unroll
    for (int nf = 0; nf < 2; nf++) {
        const int col = nt * 64 + nb + nf * 8 + tig * 2;
        *reinterpret_cast<__half2*>(&C[row * NCOLS + col]) =
            __floats2half2_rn(c[nf][0], c[nf][1]);
        *reinterpret_cast<__half2*>(&C[(row + 8) * NCOLS + col]) =
            __floats2half2_rn(c[nf][2], c[nf][3]);
    }
}

// ---------------------------------------------------------------------------
// Pairwise L1 + exp-sum, pure fp16x2 (unchanged from R8 best).
// Grid 512 = (o, i-quarter). 512 threads = 64 i-local x 8-way j-split (32 j).
// ---------------------------------------------------------------------------
__global__ __launch_bounds__(512) void pairwise_kernel(
    const __half* __restrict__ Mh, float* __restrict__ out)
{
    const int o  = blockIdx.x >> 2;
    const int iq = blockIdx.x & 3;
    const int il = threadIdx.x & 63;
    const int h  = threadIdx.x >> 6;
    const int i  = iq * 64 + il;

    __shared__ uint4 Ms[BATCH];
    __shared__ float psum[7][64];

    if (threadIdx.x < BATCH)
        Ms[threadIdx.x] = *reinterpret_cast<const uint4*>(
            &Mh[threadIdx.x * NCOLS + o * KD]);
    __syncthreads();

    uint4 av = Ms[i];
    const __half2 a0 = *reinterpret_cast<__half2*>(&av.x);
    const __half2 a1 = *reinterpret_cast<__half2*>(&av.y);
    const __half2 a2 = *reinterpret_cast<__half2*>(&av.z);
    const __half2 a3 = *reinterpret_cast<__half2*>(&av.w);

    const __half2 nlog2e = __float2half2_rn(-1.44269504089f);
    __half2 acc = __float2half2_rn(0.0f);

    const int j0 = h * 32;
    #pragma unroll 8
    for (int j = j0; j < j0 + 32; j++) {
        uint4 bv = Ms[j];
        const __half2 s0 = __hsub2(a0, *reinterpret_cast<__half2*>(&bv.x));
        const __half2 s1 = __hsub2(a1, *reinterpret_cast<__half2*>(&bv.y));
        const __half2 s2 = __hsub2(a2, *reinterpret_cast<__half2*>(&bv.z));
        const __half2 s3 = __hsub2(a3, *reinterpret_cast<__half2*>(&bv.w));
        const __half2 t = __hadd2(__hadd2(__habs2(s0), __habs2(s1)),
                                  __hadd2(__habs2(s2), __habs2(s3)));
        const __half2 d = __hadd2(t, __lowhigh2highlow(t));
        acc = __hadd2(acc, h2exp2(__hmul2(d, nlog2e)));
    }

    const float s = __low2float(acc);

    if (h) psum[h - 1][il] = s;
    __syncthreads();
    if (h == 0) {
        float tot = s - 1.0f;
        #pragma unroll
        for (int q = 0; q < 7; q++) tot += psum[q][il];
        out[i * OUTW + INF + o] = tot;
    }
}

// ---------------------------------------------------------------------------
extern "C" void kernel_launch(void* const* d_in, const int* in_sizes, int n_in,
                              void* d_out, int out_size)
{
    const float* x = (const float*)d_in[0];   // (256, 1024)
    const float* T = (const float*)d_in[1];   // (1024, 1024)
    float* out = (float*)d_out;               // (256, 1152)

    __half* Mh;
    cudaGetSymbolAddress((void**)&Mh, g_Mh);

    gemm_copy_kernel<<<144, 256>>>(x, T, out, Mh);
    pairwise_kernel<<<4 * OUTF, 512>>>(Mh, out);
}